// round 1
// baseline (speedup 1.0000x reference)
#include <cuda_runtime.h>

#define BB 4
#define CC 64
#define HH 128
#define WW 128
#define LL 4
#define NOFF 18

// ---------------- scratch (static __device__, no allocation) ----------------
__device__ float g_xnhwc[BB*HH*WW*CC];          // x transposed to NHWC (level-0 input)
__device__ float g_curN [BB*HH*WW*CC];          // downsampled gated input for level>0
__device__ float g_off  [BB*HH*WW*NOFF];        // offset conv output, [b,y,x,18]
__device__ float g_dc   [BB*HH*WW*CC];          // deform conv output (pre-gate), NHWC
__device__ float g_feats[LL][BB*HH*WW*CC];      // gated+upsampled per level, NHWC
__device__ float g_gates[BB*CC];                // SE gates for current level
__device__ float g_wcum [CC*LL*CC];             // cumulative fuse weights [o][j][c]
__device__ float g_offWT[LL*9*NOFF*CC];         // off weights transposed [l][k][o][c]
__device__ float g_dcWT [LL*CC*9*CC];           // dc  weights transposed [l][o][k][c]

// ---------------- prep: weight transposes + cumulative fuse weights ----------
__global__ void prep_k(const float* __restrict__ off_w,
                       const float* __restrict__ dc_w,
                       const float* __restrict__ fuse_w)
{
    int i = blockIdx.x * blockDim.x + threadIdx.x;
    if (i < LL*CC*9*CC) {               // dcWT[l][(o*9+k)*64+c] = dc_w[l][o][c][k]
        int c = i & 63; int r = i >> 6; int k = r % 9; int q = r / 9;
        int o = q & 63; int l = q >> 6;
        g_dcWT[i] = dc_w[(((l*CC + o)*CC + c)*9) + k];
    }
    if (i < LL*9*NOFF*CC) {             // offWT[l][(k*18+o)*64+c] = off_w[l][o][c][k]
        int c = i & 63; int r = i >> 6; int o = r % NOFF; int q = r / NOFF;
        int k = q % 9; int l = q / 9;
        g_offWT[i] = off_w[(((l*NOFF + o)*CC + c)*9) + k];
    }
    if (i < CC*LL*CC) {                 // wcum[o][j][c] = sum_{t<=j} fuse_w[o][t*64+c]
        int c = i & 63; int r = i >> 6; int j = r & 3; int o = r >> 2;
        float s = 0.f;
        for (int t = 0; t <= j; t++) s += fuse_w[o*(LL*CC) + t*CC + c];
        g_wcum[i] = s;
    }
}

// ---------------- NCHW -> NHWC transpose of x --------------------------------
__global__ void to_nhwc_k(const float* __restrict__ x)
{
    int i = blockIdx.x * blockDim.x + threadIdx.x;
    if (i >= BB*HH*WW*CC) return;
    int c = i & 63; int p = i >> 6;
    int xx = p & 127; p >>= 7; int y = p & 127; int b = p >> 7;
    g_xnhwc[i] = x[((b*CC + c)*HH + y)*WW + xx];
}

// ---------------- 2x2 avg-pool of gated prev-level output --------------------
// exact bilinear half-size with align_corners=False == 2x2 average
__global__ void down_k(int h, int w)   // h,w: OUTPUT size; input is 2h x 2w
{
    int i = blockIdx.x * blockDim.x + threadIdx.x;
    int total = BB*h*w*CC;
    if (i >= total) return;
    int c = i & 63; int p = i >> 6;
    int x = p % w; int t = p / w; int y = t % h; int b = t / h;
    int W2 = 2*w;
    float g = g_gates[b*CC + c];
    size_t base = ((size_t)(b*(2*h) + 2*y)*W2 + 2*x)*CC + c;
    float v = g_dc[base] + g_dc[base + CC] + g_dc[base + (size_t)W2*CC] + g_dc[base + (size_t)W2*CC + CC];
    g_curN[i] = 0.25f * g * v;
}

// ---------------- 3x3 offset conv (NHWC in, [b,y,x,18] out) ------------------
__global__ void offconv_k(const float* __restrict__ off_b, int lvl, int h, int w, int use_x)
{
    int i = blockIdx.x * blockDim.x + threadIdx.x;
    int total = BB*h*w*NOFF;
    if (i >= total) return;
    int o = i % NOFF; int p = i / NOFF;
    int x = p % w; int t = p / w; int y = t % h; int b = t / h;
    const float* src = use_x ? g_xnhwc : g_curN;
    float acc = off_b[lvl*NOFF + o];
    for (int ky = 0; ky < 3; ky++) {
        int yy = y + ky - 1;
        if ((unsigned)yy >= (unsigned)h) continue;
        for (int kx = 0; kx < 3; kx++) {
            int xx = x + kx - 1;
            if ((unsigned)xx >= (unsigned)w) continue;
            const float4* ip = (const float4*)(src + ((size_t)(b*h + yy)*w + xx)*CC);
            const float4* wp = (const float4*)(g_offWT + (((lvl*9 + ky*3+kx)*NOFF) + o)*CC);
            #pragma unroll
            for (int j = 0; j < 16; j++) {
                float4 a = ip[j], ww = wp[j];
                acc += a.x*ww.x + a.y*ww.y + a.z*ww.z + a.w*ww.w;
            }
        }
    }
    g_off[(size_t)p*NOFF + o] = acc;
}

// ---------------- deformable 3x3 conv: one block per pixel -------------------
__global__ void deform_k(const float* __restrict__ dc_b, int lvl, int h, int w, int use_x)
{
    __shared__ int   s_y0[9], s_x0[9];
    __shared__ float s_wy[9], s_wx[9];
    __shared__ float s_val[9*CC];       // [k][c]
    int p = blockIdx.x;
    int c = threadIdx.x;                // 0..63
    int x = p % w; int t = p / w; int y = t % h; int b = t / h;
    const float* src = use_x ? g_xnhwc : g_curN;

    if (c < 9) {
        int k = c;
        float dy = g_off[(size_t)p*NOFF + 2*k];
        float dx = g_off[(size_t)p*NOFF + 2*k + 1];
        float py = (float)y + (float)(k/3 - 1) + dy;
        float px = (float)x + (float)(k%3 - 1) + dx;
        float y0f = floorf(py), x0f = floorf(px);
        s_y0[k] = (int)y0f; s_x0[k] = (int)x0f;
        s_wy[k] = py - y0f; s_wx[k] = px - x0f;
    }
    __syncthreads();

    const float* sb = src + (size_t)b*h*w*CC + c;
    #pragma unroll
    for (int k = 0; k < 9; k++) {
        int y0 = s_y0[k], x0 = s_x0[k];
        float wy = s_wy[k], wx = s_wx[k];
        bool yi0 = (unsigned)y0       < (unsigned)h;
        bool yi1 = (unsigned)(y0 + 1) < (unsigned)h;
        bool xi0 = (unsigned)x0       < (unsigned)w;
        bool xi1 = (unsigned)(x0 + 1) < (unsigned)w;
        float v = 0.f;
        if (yi0 && xi0) v += (1.f-wy)*(1.f-wx) * sb[((size_t)y0    *w + x0    )*CC];
        if (yi0 && xi1) v += (1.f-wy)*wx       * sb[((size_t)y0    *w + x0 + 1)*CC];
        if (yi1 && xi0) v += wy*(1.f-wx)       * sb[((size_t)(y0+1)*w + x0    )*CC];
        if (yi1 && xi1) v += wy*wx             * sb[((size_t)(y0+1)*w + x0 + 1)*CC];
        s_val[k*CC + c] = v;
    }
    __syncthreads();

    // matvec: out_o = bias_o + sum_{k,c} wT[o][k][c] * val[k][c]   (o == thread id)
    float acc = dc_b[lvl*CC + c];
    const float4* wr = (const float4*)(g_dcWT + ((size_t)lvl*CC + c)*(9*CC));
    const float4* vv = (const float4*)s_val;
    float a0=0.f, a1=0.f, a2=0.f, a3=0.f;
    #pragma unroll 8
    for (int j = 0; j < (9*CC)/4; j++) {
        float4 ww = wr[j]; float4 sv = vv[j];
        a0 += ww.x*sv.x; a1 += ww.y*sv.y; a2 += ww.z*sv.z; a3 += ww.w*sv.w;
    }
    g_dc[(size_t)p*CC + c] = acc + ((a0+a1) + (a2+a3));
}

// ---------------- SE: channel means + tiny MLP -> gates ----------------------
__global__ void segate_k(const float* __restrict__ se_w1, const float* __restrict__ se_b1,
                         const float* __restrict__ se_w2, const float* __restrict__ se_b2,
                         int lvl, int h, int w)
{
    __shared__ float red[512];
    __shared__ float hid[4];
    int b   = blockIdx.x;
    int tid = threadIdx.x;           // 512 threads
    int c = tid & 63; int g = tid >> 6;  // 8 groups of 64
    int npix = h * w;
    float s = 0.f;
    for (int p = g; p < npix; p += 8)
        s += g_dc[((size_t)b*npix + p)*CC + c];
    red[tid] = s;
    __syncthreads();
    if (g == 0) {
        float m = red[c];
        for (int q = 1; q < 8; q++) m += red[q*64 + c];
        red[c] = m / (float)npix;
    }
    __syncthreads();
    if (tid < 4) {
        float a = se_b1[lvl*4 + tid];
        for (int cc = 0; cc < CC; cc++) a += se_w1[(lvl*4 + tid)*CC + cc] * red[cc];
        hid[tid] = fmaxf(a, 0.f);
    }
    __syncthreads();
    if (tid < CC) {
        float a = se_b2[lvl*CC + tid];
        #pragma unroll
        for (int r = 0; r < 4; r++) a += se_w2[(lvl*CC + tid)*4 + r] * hid[r];
        g_gates[b*CC + tid] = 1.f / (1.f + expf(-a));
    }
}

// ---------------- gate + bilinear upsample to 128x128 ------------------------
__global__ void upsample_k(int lvl, int h, int w)
{
    int i = blockIdx.x * blockDim.x + threadIdx.x;
    if (i >= BB*HH*WW*CC) return;
    int c = i & 63; int p = i >> 6;
    int X = p & 127; p >>= 7; int Y = p & 127; int b = p >> 7;
    float g = g_gates[b*CC + c];
    float v;
    if (h == HH) {
        v = g_dc[i];
    } else {
        float scy = (float)h * (1.f/128.f);
        float sy = fminf(fmaxf((Y + 0.5f)*scy - 0.5f, 0.f), (float)(h-1));
        float sx = fminf(fmaxf((X + 0.5f)*scy - 0.5f, 0.f), (float)(w-1));
        int y0 = (int)sy; int y1 = min(y0+1, h-1); float wy = sy - (float)y0;
        int x0 = (int)sx; int x1 = min(x0+1, w-1); float wx = sx - (float)x0;
        const float* base = g_dc + (size_t)b*h*w*CC + c;
        float v00 = base[((size_t)y0*w + x0)*CC];
        float v01 = base[((size_t)y0*w + x1)*CC];
        float v10 = base[((size_t)y1*w + x0)*CC];
        float v11 = base[((size_t)y1*w + x1)*CC];
        v = (1.f-wy)*((1.f-wx)*v00 + wx*v01) + wy*((1.f-wx)*v10 + wx*v11);
    }
    g_feats[lvl][i] = g * v;
}

// ---------------- fuse: cumulative 1x1 conv over 4 levels, NCHW out ----------
// out[b,o,Y,X] = fuse_b[o] + sum_j sum_c wcum[o][j][c] * feats[j][b,Y,X,c]
__global__ void fuse_k(const float* __restrict__ fuse_b, float* __restrict__ out)
{
    __shared__ float sf[16*LL*CC];      // [px][j][c], 16 pixels
    int pbase = blockIdx.x * 16;        // pixels flat (b,Y,X), X fastest
    int tid = threadIdx.x;              // 64 threads = 64 output channels
    for (int t = tid; t < 16*LL*CC; t += 64) {
        int c = t & 63; int j = (t >> 6) & 3; int px = t >> 8;
        sf[t] = g_feats[j][((size_t)(pbase + px))*CC + c];
    }
    __syncthreads();
    int o = tid;
    float acc[16];
    #pragma unroll
    for (int px = 0; px < 16; px++) acc[px] = 0.f;
    const float4* wr = (const float4*)(g_wcum + (size_t)o*(LL*CC));
    #pragma unroll 4
    for (int j = 0; j < (LL*CC)/4; j++) {
        float4 ww = wr[j];
        #pragma unroll
        for (int px = 0; px < 16; px++) {
            float4 sv = ((const float4*)(sf + px*(LL*CC)))[j];
            acc[px] += ww.x*sv.x + ww.y*sv.y + ww.z*sv.z + ww.w*sv.w;
        }
    }
    float bias = fuse_b[o];
    int X0 = pbase & 127; int r = pbase >> 7; int Y = r & 127; int b = r >> 7;
    float* op = out + (((size_t)(b*CC + o)*HH + Y)*WW + X0);
    #pragma unroll
    for (int q = 0; q < 4; q++) {
        float4 res;
        res.x = bias + acc[q*4+0];
        res.y = bias + acc[q*4+1];
        res.z = bias + acc[q*4+2];
        res.w = bias + acc[q*4+3];
        ((float4*)op)[q] = res;
    }
}

// ---------------- launch ------------------------------------------------------
extern "C" void kernel_launch(void* const* d_in, const int* in_sizes, int n_in,
                              void* d_out, int out_size)
{
    const float* x      = (const float*)d_in[0];
    const float* off_w  = (const float*)d_in[1];
    const float* off_b  = (const float*)d_in[2];
    const float* dc_w   = (const float*)d_in[3];
    const float* dc_b   = (const float*)d_in[4];
    const float* se_w1  = (const float*)d_in[5];
    const float* se_b1  = (const float*)d_in[6];
    const float* se_w2  = (const float*)d_in[7];
    const float* se_b2  = (const float*)d_in[8];
    const float* fuse_w = (const float*)d_in[9];
    const float* fuse_b = (const float*)d_in[10];
    float* out = (float*)d_out;

    prep_k<<<(LL*CC*9*CC + 255)/256, 256>>>(off_w, dc_w, fuse_w);
    to_nhwc_k<<<(BB*HH*WW*CC + 255)/256, 256>>>(x);

    for (int l = 0; l < LL; l++) {
        int h = HH >> l, w = WW >> l;
        int usex = (l == 0);
        if (l > 0)
            down_k<<<(BB*h*w*CC + 255)/256, 256>>>(h, w);
        offconv_k<<<(BB*h*w*NOFF + 255)/256, 256>>>(off_b, l, h, w, usex);
        deform_k<<<BB*h*w, 64>>>(dc_b, l, h, w, usex);
        segate_k<<<BB, 512>>>(se_w1, se_b1, se_w2, se_b2, l, h, w);
        upsample_k<<<(BB*HH*WW*CC + 255)/256, 256>>>(l, h, w);
    }
    fuse_k<<<(BB*HH*WW)/16, 64>>>(fuse_b, out);
}

// round 2
// speedup vs baseline: 3.2161x; 3.2161x over previous
#include <cuda_runtime.h>

#define BB 4
#define CC 64
#define HH 128
#define WW 128
#define LL 4
#define NOFF 18
#define TILE 16

// ---------------- scratch (static __device__, no allocation) ----------------
__device__ float g_xnhwc[BB*HH*WW*CC];          // x transposed to NHWC (level-0 input)
__device__ float g_curN [BB*HH*WW*CC];          // downsampled gated input for level>0
__device__ float g_off  [BB*HH*WW*NOFF];        // offset conv output, [b,y,x,18]
__device__ float g_dc   [BB*HH*WW*CC];          // deform conv output (pre-gate), NHWC
__device__ float g_feats[LL][BB*HH*WW*CC];      // gated+upsampled per level, NHWC
__device__ float g_gates[BB*CC];                // SE gates for current level
__device__ float g_wcum [CC*LL*CC];             // cumulative fuse weights [o][j][c]
// j-major weight layouts: [l][j][o] float4  (j indexes 144 chunks of the 576=9*64 K dim,
// K element e = k*64+c maps to (k = e>>6, c = e&63))
__device__ float g_dcW2 [LL*144*CC*4];          // deform weights, 64 outputs
__device__ float g_offW2[LL*144*32*4];          // offset weights, padded to 32 outputs

// ---------------- prep: weight re-layouts + cumulative fuse weights ----------
__global__ void prep_k(const float* __restrict__ off_w,
                       const float* __restrict__ dc_w,
                       const float* __restrict__ fuse_w)
{
    int i = blockIdx.x * blockDim.x + threadIdx.x;
    if (i < LL*144*CC*4) {              // dcW2[((l*144+j)*64+o)*4+t] = dc_w[l][o][c][k]
        int t = i & 3; int o = (i >> 2) & 63; int q = (i >> 2) >> 6;
        int j = q % 144; int l = q / 144;
        int e = j*4 + t; int k = e >> 6; int c = e & 63;
        g_dcW2[i] = dc_w[(((l*CC + o)*CC + c)*9) + k];
    }
    if (i < LL*144*32*4) {              // offW2[((l*144+j)*32+o)*4+t], o>=18 -> 0
        int t = i & 3; int o = (i >> 2) & 31; int q = (i >> 2) >> 5;
        int j = q % 144; int l = q / 144;
        int e = j*4 + t; int k = e >> 6; int c = e & 63;
        g_offW2[i] = (o < NOFF) ? off_w[(((l*NOFF + o)*CC + c)*9) + k] : 0.f;
    }
    if (i < CC*LL*CC) {                 // wcum[o][j][c] = sum_{t<=j} fuse_w[o][t*64+c]
        int c = i & 63; int r = i >> 6; int j = r & 3; int o = r >> 2;
        float s = 0.f;
        for (int t = 0; t <= j; t++) s += fuse_w[o*(LL*CC) + t*CC + c];
        g_wcum[i] = s;
    }
}

// ---------------- NCHW -> NHWC transpose of x --------------------------------
__global__ void to_nhwc_k(const float* __restrict__ x)
{
    int i = blockIdx.x * blockDim.x + threadIdx.x;
    if (i >= BB*HH*WW*CC) return;
    int c = i & 63; int p = i >> 6;
    int xx = p & 127; p >>= 7; int y = p & 127; int b = p >> 7;
    g_xnhwc[i] = x[((b*CC + c)*HH + y)*WW + xx];
}

// ---------------- 2x2 avg-pool of gated prev-level output --------------------
__global__ void down_k(int h, int w)   // h,w: OUTPUT size; input is 2h x 2w
{
    int i = blockIdx.x * blockDim.x + threadIdx.x;
    int total = BB*h*w*CC;
    if (i >= total) return;
    int c = i & 63; int p = i >> 6;
    int x = p % w; int t = p / w; int y = t % h; int b = t / h;
    int W2 = 2*w;
    float g = g_gates[b*CC + c];
    size_t base = ((size_t)(b*(2*h) + 2*y)*W2 + 2*x)*CC + c;
    float v = g_dc[base] + g_dc[base + CC] + g_dc[base + (size_t)W2*CC] + g_dc[base + (size_t)W2*CC + CC];
    g_curN[i] = 0.25f * g * v;
}

// ---------------- 3x3 offset conv: implicit GEMM, 16 px/block ----------------
__global__ void offconv_k(const float* __restrict__ off_b, int lvl, int h, int w, int use_x)
{
    __shared__ float s_val[TILE*576];       // [px][k*64+c]
    int tid = threadIdx.x;                  // 128
    int pbase = blockIdx.x * TILE;
    const float* src = use_x ? g_xnhwc : g_curN;

    // gather plain 3x3 patches
    int c = tid & 63, g = tid >> 6;         // 2 groups of 64 channel-lanes
    for (int t = g; t < TILE*9; t += 2) {
        int px = t / 9, k = t % 9;
        int p = pbase + px;
        int x = p % w; int r = p / w; int y = r % h; int b = r / h;
        int yy = y + k/3 - 1, xx = x + k%3 - 1;
        float v = 0.f;
        if ((unsigned)yy < (unsigned)h && (unsigned)xx < (unsigned)w)
            v = src[((size_t)(b*h + yy)*w + xx)*CC + c];
        s_val[px*576 + k*64 + c] = v;
    }
    __syncthreads();

    // matvec: 1 output x 4 pixels per thread (outputs padded to 32)
    int o = tid & 31; int q = tid >> 5;     // q: 0..3 -> pixels q*4..q*4+3
    float acc0 = 0.f, acc1 = 0.f, acc2 = 0.f, acc3 = 0.f;
    const float4* wbase = (const float4*)g_offW2 + (size_t)lvl*144*32;
    const float4* v4 = (const float4*)s_val;
    #pragma unroll 4
    for (int j = 0; j < 144; j++) {
        float4 wv = wbase[j*32 + o];
        float4 v0 = v4[(q*4+0)*144 + j];
        float4 v1 = v4[(q*4+1)*144 + j];
        float4 v2 = v4[(q*4+2)*144 + j];
        float4 v3 = v4[(q*4+3)*144 + j];
        acc0 += wv.x*v0.x + wv.y*v0.y + wv.z*v0.z + wv.w*v0.w;
        acc1 += wv.x*v1.x + wv.y*v1.y + wv.z*v1.z + wv.w*v1.w;
        acc2 += wv.x*v2.x + wv.y*v2.y + wv.z*v2.z + wv.w*v2.w;
        acc3 += wv.x*v3.x + wv.y*v3.y + wv.z*v3.z + wv.w*v3.w;
    }
    if (o < NOFF) {
        float bb = off_b[lvl*NOFF + o];
        g_off[(size_t)(pbase + q*4+0)*NOFF + o] = bb + acc0;
        g_off[(size_t)(pbase + q*4+1)*NOFF + o] = bb + acc1;
        g_off[(size_t)(pbase + q*4+2)*NOFF + o] = bb + acc2;
        g_off[(size_t)(pbase + q*4+3)*NOFF + o] = bb + acc3;
    }
}

// ---------------- deformable 3x3 conv: implicit GEMM, 16 px/block ------------
__global__ void deform_k(const float* __restrict__ dc_b, int lvl, int h, int w, int use_x)
{
    __shared__ float s_val[TILE*576];       // [px][k*64+c]
    __shared__ int   s_y0[TILE*9], s_x0[TILE*9];
    __shared__ float s_wy[TILE*9], s_wx[TILE*9];
    int tid = threadIdx.x;                  // 128
    int pbase = blockIdx.x * TILE;
    const float* src = use_x ? g_xnhwc : g_curN;

    // per-(px,tap) metadata
    for (int t = tid; t < TILE*9; t += 128) {
        int px = t / 9, k = t % 9;
        int p = pbase + px;
        int x = p % w; int r = p / w; int y = r % h;
        float dy = g_off[(size_t)p*NOFF + 2*k];
        float dx = g_off[(size_t)p*NOFF + 2*k + 1];
        float py = (float)(y + k/3 - 1) + dy;
        float pxx = (float)(x + k%3 - 1) + dx;
        float y0f = floorf(py), x0f = floorf(pxx);
        s_y0[t] = (int)y0f; s_x0[t] = (int)x0f;
        s_wy[t] = py - y0f; s_wx[t] = pxx - x0f;
    }
    __syncthreads();

    // bilinear gather
    int c = tid & 63, g = tid >> 6;
    for (int t = g; t < TILE*9; t += 2) {
        int px = t / 9;
        int p = pbase + px;
        int b = p / (h*w);
        const float* sb = src + (size_t)b*h*w*CC + c;
        int y0 = s_y0[t], x0 = s_x0[t];
        float wy = s_wy[t], wx = s_wx[t];
        bool yi0 = (unsigned)y0       < (unsigned)h;
        bool yi1 = (unsigned)(y0 + 1) < (unsigned)h;
        bool xi0 = (unsigned)x0       < (unsigned)w;
        bool xi1 = (unsigned)(x0 + 1) < (unsigned)w;
        float v = 0.f;
        if (yi0 && xi0) v += (1.f-wy)*(1.f-wx) * sb[((size_t)y0    *w + x0    )*CC];
        if (yi0 && xi1) v += (1.f-wy)*wx       * sb[((size_t)y0    *w + x0 + 1)*CC];
        if (yi1 && xi0) v += wy*(1.f-wx)       * sb[((size_t)(y0+1)*w + x0    )*CC];
        if (yi1 && xi1) v += wy*wx             * sb[((size_t)(y0+1)*w + x0 + 1)*CC];
        s_val[(t/9)*576 + (t%9)*64 + c] = v;
    }
    __syncthreads();

    // matvec: 2 outputs x 4 pixels per thread
    int o2 = tid & 31; int q = tid >> 5;    // q: 0..3 -> pixels q*4..q*4+3
    float a00=0,a01=0,a02=0,a03=0, a10=0,a11=0,a12=0,a13=0;
    const float4* wbase = (const float4*)g_dcW2 + (size_t)lvl*144*64;
    const float4* v4 = (const float4*)s_val;
    #pragma unroll 2
    for (int j = 0; j < 144; j++) {
        float4 wa = wbase[j*64 + 2*o2];
        float4 wb = wbase[j*64 + 2*o2 + 1];
        float4 v0 = v4[(q*4+0)*144 + j];
        float4 v1 = v4[(q*4+1)*144 + j];
        float4 v2 = v4[(q*4+2)*144 + j];
        float4 v3 = v4[(q*4+3)*144 + j];
        a00 += wa.x*v0.x + wa.y*v0.y + wa.z*v0.z + wa.w*v0.w;
        a01 += wa.x*v1.x + wa.y*v1.y + wa.z*v1.z + wa.w*v1.w;
        a02 += wa.x*v2.x + wa.y*v2.y + wa.z*v2.z + wa.w*v2.w;
        a03 += wa.x*v3.x + wa.y*v3.y + wa.z*v3.z + wa.w*v3.w;
        a10 += wb.x*v0.x + wb.y*v0.y + wb.z*v0.z + wb.w*v0.w;
        a11 += wb.x*v1.x + wb.y*v1.y + wb.z*v1.z + wb.w*v1.w;
        a12 += wb.x*v2.x + wb.y*v2.y + wb.z*v2.z + wb.w*v2.w;
        a13 += wb.x*v3.x + wb.y*v3.y + wb.z*v3.z + wb.w*v3.w;
    }
    float b0 = dc_b[lvl*CC + 2*o2];
    float b1 = dc_b[lvl*CC + 2*o2 + 1];
    float2* outp = (float2*)g_dc;
    outp[(size_t)(pbase + q*4+0)*32 + o2] = make_float2(b0 + a00, b1 + a10);
    outp[(size_t)(pbase + q*4+1)*32 + o2] = make_float2(b0 + a01, b1 + a11);
    outp[(size_t)(pbase + q*4+2)*32 + o2] = make_float2(b0 + a02, b1 + a12);
    outp[(size_t)(pbase + q*4+3)*32 + o2] = make_float2(b0 + a03, b1 + a13);
}

// ---------------- SE: channel means + tiny MLP -> gates ----------------------
__global__ void segate_k(const float* __restrict__ se_w1, const float* __restrict__ se_b1,
                         const float* __restrict__ se_w2, const float* __restrict__ se_b2,
                         int lvl, int h, int w)
{
    __shared__ float red[512];
    __shared__ float hid[4];
    int b   = blockIdx.x;
    int tid = threadIdx.x;           // 512 threads
    int c = tid & 63; int g = tid >> 6;  // 8 groups of 64
    int npix = h * w;
    float s = 0.f;
    for (int p = g; p < npix; p += 8)
        s += g_dc[((size_t)b*npix + p)*CC + c];
    red[tid] = s;
    __syncthreads();
    if (g == 0) {
        float m = red[c];
        for (int q = 1; q < 8; q++) m += red[q*64 + c];
        red[c] = m / (float)npix;
    }
    __syncthreads();
    if (tid < 4) {
        float a = se_b1[lvl*4 + tid];
        for (int cc = 0; cc < CC; cc++) a += se_w1[(lvl*4 + tid)*CC + cc] * red[cc];
        hid[tid] = fmaxf(a, 0.f);
    }
    __syncthreads();
    if (tid < CC) {
        float a = se_b2[lvl*CC + tid];
        #pragma unroll
        for (int r = 0; r < 4; r++) a += se_w2[(lvl*CC + tid)*4 + r] * hid[r];
        g_gates[b*CC + tid] = 1.f / (1.f + expf(-a));
    }
}

// ---------------- gate + bilinear upsample to 128x128 ------------------------
__global__ void upsample_k(int lvl, int h, int w)
{
    int i = blockIdx.x * blockDim.x + threadIdx.x;
    if (i >= BB*HH*WW*CC) return;
    int c = i & 63; int p = i >> 6;
    int X = p & 127; p >>= 7; int Y = p & 127; int b = p >> 7;
    float g = g_gates[b*CC + c];
    float v;
    if (h == HH) {
        v = g_dc[i];
    } else {
        float scy = (float)h * (1.f/128.f);
        float sy = fminf(fmaxf((Y + 0.5f)*scy - 0.5f, 0.f), (float)(h-1));
        float sx = fminf(fmaxf((X + 0.5f)*scy - 0.5f, 0.f), (float)(w-1));
        int y0 = (int)sy; int y1 = min(y0+1, h-1); float wy = sy - (float)y0;
        int x0 = (int)sx; int x1 = min(x0+1, w-1); float wx = sx - (float)x0;
        const float* base = g_dc + (size_t)b*h*w*CC + c;
        float v00 = base[((size_t)y0*w + x0)*CC];
        float v01 = base[((size_t)y0*w + x1)*CC];
        float v10 = base[((size_t)y1*w + x0)*CC];
        float v11 = base[((size_t)y1*w + x1)*CC];
        v = (1.f-wy)*((1.f-wx)*v00 + wx*v01) + wy*((1.f-wx)*v10 + wx*v11);
    }
    g_feats[lvl][i] = g * v;
}

// ---------------- fuse: cumulative 1x1 conv over 4 levels, NCHW out ----------
__global__ void fuse_k(const float* __restrict__ fuse_b, float* __restrict__ out)
{
    __shared__ float sf[16*LL*CC];      // [px][j][c], 16 pixels
    int pbase = blockIdx.x * 16;        // pixels flat (b,Y,X), X fastest
    int tid = threadIdx.x;              // 64 threads = 64 output channels
    for (int t = tid; t < 16*LL*CC; t += 64) {
        int c = t & 63; int j = (t >> 6) & 3; int px = t >> 8;
        sf[t] = g_feats[j][((size_t)(pbase + px))*CC + c];
    }
    __syncthreads();
    int o = tid;
    float acc[16];
    #pragma unroll
    for (int px = 0; px < 16; px++) acc[px] = 0.f;
    const float4* wr = (const float4*)(g_wcum + (size_t)o*(LL*CC));
    #pragma unroll 4
    for (int j = 0; j < (LL*CC)/4; j++) {
        float4 ww = wr[j];
        #pragma unroll
        for (int px = 0; px < 16; px++) {
            float4 sv = ((const float4*)(sf + px*(LL*CC)))[j];
            acc[px] += ww.x*sv.x + ww.y*sv.y + ww.z*sv.z + ww.w*sv.w;
        }
    }
    float bias = fuse_b[o];
    int X0 = pbase & 127; int r = pbase >> 7; int Y = r & 127; int b = r >> 7;
    float* op = out + (((size_t)(b*CC + o)*HH + Y)*WW + X0);
    #pragma unroll
    for (int q = 0; q < 4; q++) {
        float4 res;
        res.x = bias + acc[q*4+0];
        res.y = bias + acc[q*4+1];
        res.z = bias + acc[q*4+2];
        res.w = bias + acc[q*4+3];
        ((float4*)op)[q] = res;
    }
}

// ---------------- launch ------------------------------------------------------
extern "C" void kernel_launch(void* const* d_in, const int* in_sizes, int n_in,
                              void* d_out, int out_size)
{
    const float* x      = (const float*)d_in[0];
    const float* off_w  = (const float*)d_in[1];
    const float* off_b  = (const float*)d_in[2];
    const float* dc_w   = (const float*)d_in[3];
    const float* dc_b   = (const float*)d_in[4];
    const float* se_w1  = (const float*)d_in[5];
    const float* se_b1  = (const float*)d_in[6];
    const float* se_w2  = (const float*)d_in[7];
    const float* se_b2  = (const float*)d_in[8];
    const float* fuse_w = (const float*)d_in[9];
    const float* fuse_b = (const float*)d_in[10];
    float* out = (float*)d_out;

    prep_k<<<(LL*144*CC*4 + 255)/256, 256>>>(off_w, dc_w, fuse_w);
    to_nhwc_k<<<(BB*HH*WW*CC + 255)/256, 256>>>(x);

    for (int l = 0; l < LL; l++) {
        int h = HH >> l, w = WW >> l;
        int usex = (l == 0);
        if (l > 0)
            down_k<<<(BB*h*w*CC + 255)/256, 256>>>(h, w);
        offconv_k<<<(BB*h*w)/TILE, 128>>>(off_b, l, h, w, usex);
        deform_k<<<(BB*h*w)/TILE, 128>>>(dc_b, l, h, w, usex);
        segate_k<<<BB, 512>>>(se_w1, se_b1, se_w2, se_b2, l, h, w);
        upsample_k<<<(BB*HH*WW*CC + 255)/256, 256>>>(l, h, w);
    }
    fuse_k<<<(BB*HH*WW)/16, 64>>>(fuse_b, out);
}

// round 3
// speedup vs baseline: 5.0477x; 1.5695x over previous
#include <cuda_runtime.h>
#include <cuda_bf16.h>

#define BB 4
#define CC 64
#define HH 128
#define WW 128
#define LL 4
#define NOFF 18

// ---------------- scratch ----------------
__device__ float g_xnhwc[BB*HH*WW*CC];
__device__ float g_curN [BB*HH*WW*CC];
__device__ float g_off  [BB*HH*WW*NOFF];
__device__ float g_dc   [BB*HH*WW*CC];
__device__ float g_feats[LL][BB*HH*WW*CC];
__device__ float g_gates[BB*CC];
__device__ float g_sum  [BB*CC];
__device__ float g_wcumT[64*64*4];          // [j][o] float4 of cumulative fuse weights
__device__ unsigned g_WdHi[LL*9*32*64];     // deform W, [l][tap][c2][o] packed bf16x2 (hi)
__device__ unsigned g_WdLo[LL*9*32*64];     // (lo)
__device__ unsigned g_WoHi[LL*9*32*32];     // offset W padded to 32 outputs
__device__ unsigned g_WoLo[LL*9*32*32];

__device__ __forceinline__ unsigned pack_bf16_hi(float v0, float v1, float& r0, float& r1) {
    __nv_bfloat16 h0 = __float2bfloat16_rn(v0);
    __nv_bfloat16 h1 = __float2bfloat16_rn(v1);
    r0 = v0 - __bfloat162float(h0);
    r1 = v1 - __bfloat162float(h1);
    return ((unsigned)__bfloat16_as_ushort(h1) << 16) | (unsigned)__bfloat16_as_ushort(h0);
}
__device__ __forceinline__ unsigned pack_bf16(float v0, float v1) {
    __nv_bfloat16 h0 = __float2bfloat16_rn(v0);
    __nv_bfloat16 h1 = __float2bfloat16_rn(v1);
    return ((unsigned)__bfloat16_as_ushort(h1) << 16) | (unsigned)__bfloat16_as_ushort(h0);
}
__device__ __forceinline__ void split2(float v0, float v1, unsigned& hi, unsigned& lo) {
    float r0, r1;
    hi = pack_bf16_hi(v0, v1, r0, r1);
    lo = pack_bf16(r0, r1);
}

__device__ __forceinline__ void mma_bf16(float c[4], const unsigned a[4], const unsigned b[2]) {
    asm volatile("mma.sync.aligned.m16n8k16.row.col.f32.bf16.bf16.f32 "
        "{%0,%1,%2,%3}, {%4,%5,%6,%7}, {%8,%9}, {%0,%1,%2,%3};"
        : "+f"(c[0]), "+f"(c[1]), "+f"(c[2]), "+f"(c[3])
        : "r"(a[0]), "r"(a[1]), "r"(a[2]), "r"(a[3]), "r"(b[0]), "r"(b[1]));
}

// ---------------- prep ----------------
__global__ void prep_k(const float* __restrict__ off_w,
                       const float* __restrict__ dc_w,
                       const float* __restrict__ fuse_w)
{
    int i = blockIdx.x * blockDim.x + threadIdx.x;
    if (i < LL*9*32*64) {
        int o = i & 63; int r = i >> 6; int c2 = r & 31; r >>= 5;
        int tap = r % 9; int l = r / 9;
        float v0 = dc_w[(((l*CC + o)*CC) + 2*c2)*9 + tap];
        float v1 = dc_w[(((l*CC + o)*CC) + 2*c2 + 1)*9 + tap];
        unsigned hi, lo; split2(v0, v1, hi, lo);
        g_WdHi[i] = hi; g_WdLo[i] = lo;
    }
    if (i < LL*9*32*32) {
        int o = i & 31; int r = i >> 5; int c2 = r & 31; r >>= 5;
        int tap = r % 9; int l = r / 9;
        float v0 = 0.f, v1 = 0.f;
        if (o < NOFF) {
            v0 = off_w[(((l*NOFF + o)*CC) + 2*c2)*9 + tap];
            v1 = off_w[(((l*NOFF + o)*CC) + 2*c2 + 1)*9 + tap];
        }
        unsigned hi, lo; split2(v0, v1, hi, lo);
        g_WoHi[i] = hi; g_WoLo[i] = lo;
    }
    if (i < 64*64*4) {                     // wcumT[(j*64+o)*4+t]
        int t = i & 3; int o = (i >> 2) & 63; int j = i >> 8;
        int e = j*4 + t; int lev = e >> 6; int c = e & 63;
        float s = 0.f;
        for (int u = 0; u <= lev; u++) s += fuse_w[o*(LL*CC) + u*CC + c];
        g_wcumT[i] = s;
    }
}

// ---------------- NCHW -> NHWC ----------------
__global__ void to_nhwc_k(const float* __restrict__ x)
{
    int i = blockIdx.x * blockDim.x + threadIdx.x;
    if (i >= BB*HH*WW*CC) return;
    int c = i & 63; int p = i >> 6;
    int xx = p & 127; p >>= 7; int y = p & 127; int b = p >> 7;
    g_xnhwc[i] = x[((b*CC + c)*HH + y)*WW + xx];
}

// ---------------- 2x2 avg-pool + gate of prev level ----------------
__global__ void down_k(int h, int w)
{
    int i = blockIdx.x * blockDim.x + threadIdx.x;
    int total = BB*h*w*CC;
    if (i >= total) return;
    int c = i & 63; int p = i >> 6;
    int x = p % w; int t = p / w; int y = t % h; int b = t / h;
    int W2 = 2*w;
    float g = g_gates[b*CC + c];
    size_t base = ((size_t)(b*(2*h) + 2*y)*W2 + 2*x)*CC + c;
    float v = g_dc[base] + g_dc[base + CC] + g_dc[base + (size_t)W2*CC] + g_dc[base + (size_t)W2*CC + CC];
    g_curN[i] = 0.25f * g * v;
}

// ---------------- unified conv via tensor cores (MODE 0=offset, 1=deform) ----
template<int MODE>
__global__ void __launch_bounds__(256, 3) conv_mma_k(const float* __restrict__ bias,
                                                     int lvl, int h, int w, int use_x)
{
    constexpr int NO   = MODE ? 64 : 32;
    constexpr int NPAD = MODE ? 66 : 34;
    constexpr int NB   = MODE ? 4  : 2;
    extern __shared__ char smem_raw[];
    unsigned* Vhi = (unsigned*)smem_raw;              // [128][34]
    unsigned* Vlo = Vhi + 128*34;
    unsigned* Whi = Vlo + 128*34;                     // [32][NPAD]
    unsigned* Wlo = Whi + 32*NPAD;
    int*   s_y0 = (int*)(Wlo + 32*NPAD);
    int*   s_x0 = s_y0 + 128*9;
    float* s_wy = (float*)(s_x0 + 128*9);
    float* s_wx = s_wy + 128*9;

    int tid = threadIdx.x;
    int lane = tid & 31, warp = tid >> 5;
    int wm = warp & 3, wn = warp >> 2;
    int t4 = lane & 3, l4 = lane >> 2;
    int pbase = blockIdx.x * 128;
    const float* src = use_x ? g_xnhwc : g_curN;
    int hw = h * w;

    if (MODE) {
        for (int t = tid; t < 128*9; t += 256) {
            int px = t / 9, k = t % 9;
            int p = pbase + px;
            int x = p % w; int r = p / w; int y = r % h;
            float dy = g_off[(size_t)p*NOFF + 2*k];
            float dx = g_off[(size_t)p*NOFF + 2*k + 1];
            float py  = (float)(y + k/3 - 1) + dy;
            float pxx = (float)(x + k%3 - 1) + dx;
            float y0f = floorf(py), x0f = floorf(pxx);
            s_y0[t] = (int)y0f; s_x0[t] = (int)x0f;
            s_wy[t] = py - y0f; s_wx[t] = pxx - x0f;
        }
    }

    float acc[2][NB][4];
    #pragma unroll
    for (int m = 0; m < 2; m++)
        #pragma unroll
        for (int n = 0; n < NB; n++)
            #pragma unroll
            for (int q = 0; q < 4; q++) acc[m][n][q] = 0.f;

    const unsigned* WHg = MODE ? g_WdHi : g_WoHi;
    const unsigned* WLg = MODE ? g_WdLo : g_WoLo;

    for (int tap = 0; tap < 9; tap++) {
        __syncthreads();
        // stage weights for this tap
        {
            const unsigned* sH = WHg + (size_t)(lvl*9 + tap)*32*NO;
            const unsigned* sL = WLg + (size_t)(lvl*9 + tap)*32*NO;
            for (int t = tid; t < 32*NO; t += 256) {
                int c2 = t / NO, o = t - c2*NO;
                Whi[c2*NPAD + o] = sH[t];
                Wlo[c2*NPAD + o] = sL[t];
            }
        }
        // stage V (gathered, bf16 hi/lo split)
        {
            int c2 = tid & 31; int ps = tid >> 5;
            for (int px = ps; px < 128; px += 8) {
                int p = pbase + px;
                float v0 = 0.f, v1 = 0.f;
                if (MODE) {
                    int b = p / hw;
                    int mt = px*9 + tap;
                    const float* sb = src + (size_t)b*hw*CC + 2*c2;
                    int y0 = s_y0[mt], x0 = s_x0[mt];
                    float wy = s_wy[mt], wx = s_wx[mt];
                    bool yi0 = (unsigned)y0       < (unsigned)h;
                    bool yi1 = (unsigned)(y0 + 1) < (unsigned)h;
                    bool xi0 = (unsigned)x0       < (unsigned)w;
                    bool xi1 = (unsigned)(x0 + 1) < (unsigned)w;
                    if (yi0 && xi0) { float2 q = *(const float2*)(sb + ((size_t)y0    *w + x0    )*CC); float cw = (1.f-wy)*(1.f-wx); v0 += cw*q.x; v1 += cw*q.y; }
                    if (yi0 && xi1) { float2 q = *(const float2*)(sb + ((size_t)y0    *w + x0 + 1)*CC); float cw = (1.f-wy)*wx;       v0 += cw*q.x; v1 += cw*q.y; }
                    if (yi1 && xi0) { float2 q = *(const float2*)(sb + ((size_t)(y0+1)*w + x0    )*CC); float cw = wy*(1.f-wx);       v0 += cw*q.x; v1 += cw*q.y; }
                    if (yi1 && xi1) { float2 q = *(const float2*)(sb + ((size_t)(y0+1)*w + x0 + 1)*CC); float cw = wy*wx;             v0 += cw*q.x; v1 += cw*q.y; }
                } else {
                    int x = p % w; int r = p / w; int y = r % h; int b = r / h;
                    int yy = y + tap/3 - 1, xx = x + tap%3 - 1;
                    if ((unsigned)yy < (unsigned)h && (unsigned)xx < (unsigned)w) {
                        float2 q = *(const float2*)(src + ((size_t)(b*h + yy)*w + xx)*CC + 2*c2);
                        v0 = q.x; v1 = q.y;
                    }
                }
                unsigned hi, lo; split2(v0, v1, hi, lo);
                Vhi[px*34 + c2] = hi;
                Vlo[px*34 + c2] = lo;
            }
        }
        __syncthreads();
        // mma: 4 k-steps (k=16) covering this tap's 64 channels
        #pragma unroll
        for (int ks = 0; ks < 4; ks++) {
            unsigned ahi[2][4], alo[2][4];
            #pragma unroll
            for (int ms = 0; ms < 2; ms++) {
                int r0 = (wm*32 + ms*16 + l4)*34 + ks*8 + t4;
                int r8 = r0 + 8*34;
                ahi[ms][0] = Vhi[r0];   ahi[ms][1] = Vhi[r8];
                ahi[ms][2] = Vhi[r0+4]; ahi[ms][3] = Vhi[r8+4];
                alo[ms][0] = Vlo[r0];   alo[ms][1] = Vlo[r8];
                alo[ms][2] = Vlo[r0+4]; alo[ms][3] = Vlo[r8+4];
            }
            #pragma unroll
            for (int nb = 0; nb < NB; nb++) {
                int o = wn*(NB*8) + nb*8 + l4;
                int wr = (ks*8 + t4)*NPAD + o;
                unsigned bhi[2] = { Whi[wr], Whi[wr + 4*NPAD] };
                unsigned blo[2] = { Wlo[wr], Wlo[wr + 4*NPAD] };
                #pragma unroll
                for (int ms = 0; ms < 2; ms++) {
                    mma_bf16(acc[ms][nb], ahi[ms], bhi);
                    mma_bf16(acc[ms][nb], alo[ms], bhi);
                    mma_bf16(acc[ms][nb], ahi[ms], blo);
                }
            }
        }
    }

    // epilogue
    #pragma unroll
    for (int ms = 0; ms < 2; ms++) {
        int px = pbase + wm*32 + ms*16 + l4;
        #pragma unroll
        for (int nb = 0; nb < NB; nb++) {
            int o = wn*(NB*8) + nb*8 + 2*t4;
            if (MODE) {
                float b0 = bias[lvl*CC + o], b1 = bias[lvl*CC + o + 1];
                *(float2*)(g_dc + (size_t)px*CC + o)       = make_float2(acc[ms][nb][0] + b0, acc[ms][nb][1] + b1);
                *(float2*)(g_dc + (size_t)(px+8)*CC + o)   = make_float2(acc[ms][nb][2] + b0, acc[ms][nb][3] + b1);
            } else {
                if (o < NOFF) {
                    float b0 = bias[lvl*NOFF + o];
                    g_off[(size_t)px*NOFF + o]     = acc[ms][nb][0] + b0;
                    g_off[(size_t)(px+8)*NOFF + o] = acc[ms][nb][2] + b0;
                }
                if (o + 1 < NOFF) {
                    float b1 = bias[lvl*NOFF + o + 1];
                    g_off[(size_t)px*NOFF + o + 1]     = acc[ms][nb][1] + b1;
                    g_off[(size_t)(px+8)*NOFF + o + 1] = acc[ms][nb][3] + b1;
                }
            }
        }
    }
}

// ---------------- SE reduce (parallel) + gate ----------------
__global__ void zero_k() { g_sum[threadIdx.x] = 0.f; }

__global__ void reduce_k(int h, int w)
{
    __shared__ float red[256];
    int blk = blockIdx.x; int b = blk >> 5; int slice = blk & 31;
    int tid = threadIdx.x;
    int c = tid & 63; int g = tid >> 6;
    int npix = h * w; int per = npix >> 5;
    float s = 0.f;
    int end = (slice + 1) * per;
    for (int p = slice*per + g; p < end; p += 4)
        s += g_dc[((size_t)b*npix + p)*CC + c];
    red[tid] = s;
    __syncthreads();
    if (g == 0) {
        float m = red[c] + red[64 + c] + red[128 + c] + red[192 + c];
        atomicAdd(&g_sum[b*CC + c], m);
    }
}

__global__ void gate_k(const float* __restrict__ se_w1, const float* __restrict__ se_b1,
                       const float* __restrict__ se_w2, const float* __restrict__ se_b2,
                       int lvl, int npix)
{
    __shared__ float mean[64];
    __shared__ float hid[4];
    int b = blockIdx.x; int tid = threadIdx.x;
    mean[tid] = g_sum[b*CC + tid] / (float)npix;
    __syncthreads();
    if (tid < 4) {
        float a = se_b1[lvl*4 + tid];
        for (int cc = 0; cc < CC; cc++) a += se_w1[(lvl*4 + tid)*CC + cc] * mean[cc];
        hid[tid] = fmaxf(a, 0.f);
    }
    __syncthreads();
    float a = se_b2[lvl*CC + tid];
    #pragma unroll
    for (int r = 0; r < 4; r++) a += se_w2[(lvl*CC + tid)*4 + r] * hid[r];
    g_gates[b*CC + tid] = 1.f / (1.f + expf(-a));
}

// ---------------- gate + bilinear upsample ----------------
__global__ void upsample_k(int lvl, int h, int w)
{
    int i = blockIdx.x * blockDim.x + threadIdx.x;
    if (i >= BB*HH*WW*CC) return;
    int c = i & 63; int p = i >> 6;
    int X = p & 127; p >>= 7; int Y = p & 127; int b = p >> 7;
    float g = g_gates[b*CC + c];
    float v;
    if (h == HH) {
        v = g_dc[i];
    } else {
        float sc = (float)h * (1.f/128.f);
        float sy = fminf(fmaxf((Y + 0.5f)*sc - 0.5f, 0.f), (float)(h-1));
        float sx = fminf(fmaxf((X + 0.5f)*sc - 0.5f, 0.f), (float)(w-1));
        int y0 = (int)sy; int y1 = min(y0+1, h-1); float wy = sy - (float)y0;
        int x0 = (int)sx; int x1 = min(x0+1, w-1); float wx = sx - (float)x0;
        const float* base = g_dc + (size_t)b*h*w*CC + c;
        float v00 = base[((size_t)y0*w + x0)*CC];
        float v01 = base[((size_t)y0*w + x1)*CC];
        float v10 = base[((size_t)y1*w + x0)*CC];
        float v11 = base[((size_t)y1*w + x1)*CC];
        v = (1.f-wy)*((1.f-wx)*v00 + wx*v01) + wy*((1.f-wx)*v10 + wx*v11);
    }
    g_feats[lvl][i] = g * v;
}

// ---------------- fuse: cumulative 1x1 over 4 levels, coalesced NCHW out -----
__global__ void fuse_k(const float* __restrict__ fuse_b, float* __restrict__ out)
{
    __shared__ float sf[32*256];        // [px][j*64+c]  (32KB)
    int pbase = blockIdx.x * 32;
    int tid = threadIdx.x;              // 256
    for (int t = tid; t < 32*256; t += 256) {
        int px = t >> 8; int jc = t & 255; int j = jc >> 6; int c = jc & 63;
        sf[t] = g_feats[j][(size_t)(pbase + px)*CC + c];
    }
    __syncthreads();
    int o = tid & 63; int pq = tid >> 6;     // 4 groups x 8 px
    float acc[8];
    #pragma unroll
    for (int q = 0; q < 8; q++) acc[q] = 0.f;
    const float4* wr = (const float4*)g_wcumT;
    #pragma unroll 4
    for (int j = 0; j < 64; j++) {
        float4 ww = wr[j*64 + o];
        #pragma unroll
        for (int q = 0; q < 8; q++) {
            float4 sv = ((const float4*)sf)[(pq*8 + q)*64 + j];
            acc[q] += ww.x*sv.x + ww.y*sv.y + ww.z*sv.z + ww.w*sv.w;
        }
    }
    float bias = fuse_b[o];
    __syncthreads();
    float* sout = sf;                    // reuse: [o][32 px]
    #pragma unroll
    for (int q = 0; q < 8; q++) sout[o*32 + pq*8 + q] = acc[q] + bias;
    __syncthreads();
    int X0 = pbase & 127; int r = pbase >> 7; int Y = r & 127; int b = r >> 7;
    for (int t = tid; t < 64*8; t += 256) {
        int oo = t >> 3; int q = t & 7;
        float4 v = ((const float4*)sout)[oo*8 + q];
        *(float4*)(out + (((size_t)(b*CC + oo)*HH + Y)*WW + X0 + q*4)) = v;
    }
}

// ---------------- launch ----------------
extern "C" void kernel_launch(void* const* d_in, const int* in_sizes, int n_in,
                              void* d_out, int out_size)
{
    const float* x      = (const float*)d_in[0];
    const float* off_w  = (const float*)d_in[1];
    const float* off_b  = (const float*)d_in[2];
    const float* dc_w   = (const float*)d_in[3];
    const float* dc_b   = (const float*)d_in[4];
    const float* se_w1  = (const float*)d_in[5];
    const float* se_b1  = (const float*)d_in[6];
    const float* se_w2  = (const float*)d_in[7];
    const float* se_b2  = (const float*)d_in[8];
    const float* fuse_w = (const float*)d_in[9];
    const float* fuse_b = (const float*)d_in[10];
    float* out = (float*)d_out;

    const int SMEM_DEF = (128*34*2 + 32*66*2)*4 + 128*9*16;   // 70144
    const int SMEM_OFF = (128*34*2 + 32*34*2)*4;              // 43520
    static int attr_done = 0;
    cudaFuncSetAttribute(conv_mma_k<1>, cudaFuncAttributeMaxDynamicSharedMemorySize, SMEM_DEF);
    cudaFuncSetAttribute(conv_mma_k<0>, cudaFuncAttributeMaxDynamicSharedMemorySize, SMEM_OFF);
    (void)attr_done;

    prep_k<<<(LL*9*32*64 + 255)/256, 256>>>(off_w, dc_w, fuse_w);
    to_nhwc_k<<<(BB*HH*WW*CC + 255)/256, 256>>>(x);

    for (int l = 0; l < LL; l++) {
        int h = HH >> l, w = WW >> l;
        int usex = (l == 0);
        int grid = (BB*h*w)/128;
        if (l > 0)
            down_k<<<(BB*h*w*CC + 255)/256, 256>>>(h, w);
        conv_mma_k<0><<<grid, 256, SMEM_OFF>>>(off_b, l, h, w, usex);
        conv_mma_k<1><<<grid, 256, SMEM_DEF>>>(dc_b, l, h, w, usex);
        zero_k<<<1, 256>>>();
        reduce_k<<<BB*32, 256>>>(h, w);
        gate_k<<<BB, 64>>>(se_w1, se_b1, se_w2, se_b2, l, h*w);
        upsample_k<<<(BB*HH*WW*CC + 255)/256, 256>>>(l, h, w);
    }
    fuse_k<<<(BB*HH*WW)/32, 256>>>(fuse_b, out);
}

// round 4
// speedup vs baseline: 7.7339x; 1.5322x over previous
#include <cuda_runtime.h>
#include <cuda_bf16.h>

#define BB 4
#define CC 64
#define HH 128
#define WW 128
#define LL 4
#define NOFF 18
#define SV 36   // V row stride in u32 (144B, 16B-aligned rows for ldmatrix)

// ---------------- scratch ----------------
__device__ float g_xnhwc[BB*HH*WW*CC];
__device__ float g_curN [BB*HH*WW*CC];
__device__ float g_off  [BB*HH*WW*NOFF];
__device__ float g_dc   [BB*HH*WW*CC];
__device__ float g_feats[LL][BB*HH*WW*CC];
__device__ float g_gates[BB*CC];
__device__ float g_part [32][BB*CC];
__device__ float g_wcumT[64*64*4];           // [j][o] float4 cumulative fuse weights
__device__ uint4 g_WdF[LL*9*1024];           // deform W fragments per tap: [(ks*2+wn)*4+nb]*32+lane
__device__ uint4 g_WoF[LL*9*512];            // offset W fragments: [(ks*2+wn)*2+nb]*32+lane

__device__ __forceinline__ unsigned pack_hi(float v0, float v1, float& r0, float& r1) {
    __nv_bfloat16 h0 = __float2bfloat16_rn(v0);
    __nv_bfloat16 h1 = __float2bfloat16_rn(v1);
    r0 = v0 - __bfloat162float(h0);
    r1 = v1 - __bfloat162float(h1);
    return ((unsigned)__bfloat16_as_ushort(h1) << 16) | (unsigned)__bfloat16_as_ushort(h0);
}
__device__ __forceinline__ unsigned pack_bf(float v0, float v1) {
    __nv_bfloat16 h0 = __float2bfloat16_rn(v0);
    __nv_bfloat16 h1 = __float2bfloat16_rn(v1);
    return ((unsigned)__bfloat16_as_ushort(h1) << 16) | (unsigned)__bfloat16_as_ushort(h0);
}
__device__ __forceinline__ void split2(float v0, float v1, unsigned& hi, unsigned& lo) {
    float r0, r1; hi = pack_hi(v0, v1, r0, r1); lo = pack_bf(r0, r1);
}

__device__ __forceinline__ void mma_bf16(float c[4], const unsigned a[4], const unsigned b[2]) {
    asm volatile("mma.sync.aligned.m16n8k16.row.col.f32.bf16.bf16.f32 "
        "{%0,%1,%2,%3}, {%4,%5,%6,%7}, {%8,%9}, {%0,%1,%2,%3};"
        : "+f"(c[0]), "+f"(c[1]), "+f"(c[2]), "+f"(c[3])
        : "r"(a[0]), "r"(a[1]), "r"(a[2]), "r"(a[3]), "r"(b[0]), "r"(b[1]));
}
__device__ __forceinline__ void ldsm4(unsigned r[4], const unsigned* ptr) {
    unsigned addr = (unsigned)__cvta_generic_to_shared(ptr);
    asm volatile("ldmatrix.sync.aligned.m8n8.x4.shared.b16 {%0,%1,%2,%3}, [%4];"
        : "=r"(r[0]), "=r"(r[1]), "=r"(r[2]), "=r"(r[3]) : "r"(addr));
}

// ---------------- prep: fragment-ordered weights + cumulative fuse ----------
__global__ void prep_k(const float* __restrict__ off_w,
                       const float* __restrict__ dc_w,
                       const float* __restrict__ fuse_w)
{
    int i = blockIdx.x * blockDim.x + threadIdx.x;
    if (i < LL*9*4*2*4*32) {            // deform fragments
        int lane = i & 31; int r = i >> 5;
        int nb = r & 3; r >>= 2; int wn = r & 1; r >>= 1;
        int ks = r & 3; r >>= 2; int tap = r % 9; int l = r / 9;
        int t4 = lane & 3, l4 = lane >> 2;
        int o = wn*32 + nb*8 + l4;
        int c2a = ks*8 + t4, c2b = c2a + 4;
        float va0 = dc_w[((l*CC + o)*CC + 2*c2a)*9 + tap];
        float va1 = dc_w[((l*CC + o)*CC + 2*c2a + 1)*9 + tap];
        float vb0 = dc_w[((l*CC + o)*CC + 2*c2b)*9 + tap];
        float vb1 = dc_w[((l*CC + o)*CC + 2*c2b + 1)*9 + tap];
        unsigned ha, la, hb, lb;
        split2(va0, va1, ha, la); split2(vb0, vb1, hb, lb);
        g_WdF[(size_t)(l*9 + tap)*1024 + ((ks*2 + wn)*4 + nb)*32 + lane] = make_uint4(ha, hb, la, lb);
    }
    if (i < LL*9*4*2*2*32) {            // offset fragments (padded outputs)
        int lane = i & 31; int r = i >> 5;
        int nb = r & 1; r >>= 1; int wn = r & 1; r >>= 1;
        int ks = r & 3; r >>= 2; int tap = r % 9; int l = r / 9;
        int t4 = lane & 3, l4 = lane >> 2;
        int o = wn*16 + nb*8 + l4;
        int c2a = ks*8 + t4, c2b = c2a + 4;
        float va0 = 0.f, va1 = 0.f, vb0 = 0.f, vb1 = 0.f;
        if (o < NOFF) {
            va0 = off_w[((l*NOFF + o)*CC + 2*c2a)*9 + tap];
            va1 = off_w[((l*NOFF + o)*CC + 2*c2a + 1)*9 + tap];
            vb0 = off_w[((l*NOFF + o)*CC + 2*c2b)*9 + tap];
            vb1 = off_w[((l*NOFF + o)*CC + 2*c2b + 1)*9 + tap];
        }
        unsigned ha, la, hb, lb;
        split2(va0, va1, ha, la); split2(vb0, vb1, hb, lb);
        g_WoF[(size_t)(l*9 + tap)*512 + ((ks*2 + wn)*2 + nb)*32 + lane] = make_uint4(ha, hb, la, lb);
    }
    if (i < 64*64*4) {                  // wcumT[(j*64+o)*4+t]
        int t = i & 3; int o = (i >> 2) & 63; int j = i >> 8;
        int e = j*4 + t; int lev = e >> 6; int c = e & 63;
        float s = 0.f;
        for (int u = 0; u <= lev; u++) s += fuse_w[o*(LL*CC) + u*CC + c];
        g_wcumT[i] = s;
    }
}

// ---------------- NCHW -> NHWC (smem-tiled transpose) ----------------
__global__ void to_nhwc_k(const float* __restrict__ x)
{
    __shared__ float t[64][33];
    int blk = blockIdx.x;               // b*HH*4 blocks
    int xt = blk & 3; int r = blk >> 2; int y = r & 127; int b = r >> 7;
    int x0 = xt * 32;
    int tid = threadIdx.x;              // 256
    int xx = tid & 31, cg = tid >> 5;
    #pragma unroll
    for (int pass = 0; pass < 8; pass++) {
        int c = pass*8 + cg;
        t[c][xx] = x[((size_t)(b*CC + c)*HH + y)*WW + x0 + xx];
    }
    __syncthreads();
    int c = tid & 63, xg = tid >> 6;
    #pragma unroll
    for (int pass = 0; pass < 8; pass++) {
        int xo = pass*4 + xg;
        g_xnhwc[((size_t)((b*HH + y)*WW) + x0 + xo)*CC + c] = t[c][xo];
    }
}

// ---------------- 2x2 avg-pool + gate ----------------
__global__ void down_k(int h, int w)
{
    int i = blockIdx.x * blockDim.x + threadIdx.x;
    int total = BB*h*w*CC;
    if (i >= total) return;
    int c = i & 63; int p = i >> 6;
    int x = p % w; int t = p / w; int y = t % h; int b = t / h;
    int W2 = 2*w;
    float g = g_gates[b*CC + c];
    size_t base = ((size_t)(b*(2*h) + 2*y)*W2 + 2*x)*CC + c;
    float v = g_dc[base] + g_dc[base + CC] + g_dc[base + (size_t)W2*CC] + g_dc[base + (size_t)W2*CC + CC];
    g_curN[i] = 0.25f * g * v;
}

// ---------------- unified conv via mma + ldmatrix, 64 px/block ---------------
// MODE 0 = offset conv (32 padded outputs), MODE 1 = deform conv (64 outputs)
template<int MODE>
__global__ void __launch_bounds__(256, MODE ? 2 : 4) conv_mma_k(
    const float* __restrict__ bias, int lvl, int h, int w, int use_x)
{
    constexpr int NB    = MODE ? 4 : 2;
    constexpr int WFRAG = MODE ? 1024 : 512;   // uint4 per tap
    extern __shared__ unsigned smem[];
    // V buffers: hi[buf], lo[buf] each 64*SV u32
    unsigned* Vh[2] = { smem, smem + 2304 };
    unsigned* Vl[2] = { smem + 4608, smem + 6912 };
    uint4* Wf = (uint4*)(smem + 9216);         // [buf][WFRAG]
    unsigned* mb = smem + 9216 + 8*WFRAG;      // meta (MODE 1 only)
    int*   s_y0 = (int*)mb;
    int*   s_x0 = s_y0 + 576;
    float* s_wy = (float*)(s_x0 + 576);
    float* s_wx = s_wy + 576;

    int tid = threadIdx.x;
    int lane = tid & 31, warp = tid >> 5;
    int wm = warp & 3, wn = warp >> 2;
    int t4 = lane & 3, l4 = lane >> 2;
    int pbase = blockIdx.x * 64;
    const float* src = use_x ? g_xnhwc : g_curN;
    int hw = h * w;
    int b = pbase / hw;                        // constant within block
    const float* sb0 = src + (size_t)b*hw*CC;

    if (MODE) {
        for (int t = tid; t < 64*9; t += 256) {
            int px = t / 9, k = t % 9;
            int p = pbase + px;
            int x = p % w; int y = (p / w) % h;
            float dy = g_off[(size_t)p*NOFF + 2*k];
            float dx = g_off[(size_t)p*NOFF + 2*k + 1];
            float py  = (float)(y + k/3 - 1) + dy;
            float pxx = (float)(x + k%3 - 1) + dx;
            float y0f = floorf(py), x0f = floorf(pxx);
            s_y0[t] = (int)y0f; s_x0[t] = (int)x0f;
            s_wy[t] = py - y0f; s_wx[t] = pxx - x0f;
        }
        __syncthreads();
    }

    const uint4* Wsrc = (MODE ? g_WdF : g_WoF) + (size_t)lvl*9*WFRAG;
    int c4 = lane & 15, pxo = lane >> 4;

    // ---- staging lambdas (inlined manually via macros of code blocks) ----
    #define STAGE(tap_, buf_) {                                                   \
        const uint4* sw = Wsrc + (size_t)(tap_)*WFRAG;                            \
        for (int i = tid; i < WFRAG; i += 256) Wf[(buf_)*WFRAG + i] = sw[i];      \
        for (int step = 0; step < 4; step++) {                                    \
            int px = step*16 + warp*2 + pxo;                                      \
            int p = pbase + px;                                                   \
            float v0 = 0.f, v1 = 0.f, v2 = 0.f, v3 = 0.f;                         \
            if (MODE) {                                                           \
                int mt = px*9 + (tap_);                                           \
                const float* sb = sb0 + 4*c4;                                     \
                int y0 = s_y0[mt], x0 = s_x0[mt];                                 \
                float wy = s_wy[mt], wx = s_wx[mt];                               \
                bool yi0 = (unsigned)y0       < (unsigned)h;                      \
                bool yi1 = (unsigned)(y0 + 1) < (unsigned)h;                      \
                bool xi0 = (unsigned)x0       < (unsigned)w;                      \
                bool xi1 = (unsigned)(x0 + 1) < (unsigned)w;                      \
                if (yi0 && xi0) { float4 q = *(const float4*)(sb + ((size_t)y0    *w + x0    )*CC); float cw = (1.f-wy)*(1.f-wx); v0 += cw*q.x; v1 += cw*q.y; v2 += cw*q.z; v3 += cw*q.w; } \
                if (yi0 && xi1) { float4 q = *(const float4*)(sb + ((size_t)y0    *w + x0 + 1)*CC); float cw = (1.f-wy)*wx;       v0 += cw*q.x; v1 += cw*q.y; v2 += cw*q.z; v3 += cw*q.w; } \
                if (yi1 && xi0) { float4 q = *(const float4*)(sb + ((size_t)(y0+1)*w + x0    )*CC); float cw = wy*(1.f-wx);       v0 += cw*q.x; v1 += cw*q.y; v2 += cw*q.z; v3 += cw*q.w; } \
                if (yi1 && xi1) { float4 q = *(const float4*)(sb + ((size_t)(y0+1)*w + x0 + 1)*CC); float cw = wy*wx;             v0 += cw*q.x; v1 += cw*q.y; v2 += cw*q.z; v3 += cw*q.w; } \
            } else {                                                              \
                int x = p % w; int y = (p / w) % h;                               \
                int yy = y + (tap_)/3 - 1, xx = x + (tap_)%3 - 1;                 \
                if ((unsigned)yy < (unsigned)h && (unsigned)xx < (unsigned)w) {   \
                    float4 q = *(const float4*)(sb0 + ((size_t)yy*w + xx)*CC + 4*c4); \
                    v0 = q.x; v1 = q.y; v2 = q.z; v3 = q.w;                       \
                }                                                                 \
            }                                                                     \
            unsigned h0, l0, h1, l1;                                              \
            split2(v0, v1, h0, l0); split2(v2, v3, h1, l1);                       \
            *(uint2*)&Vh[buf_][px*SV + 2*c4] = make_uint2(h0, h1);                \
            *(uint2*)&Vl[buf_][px*SV + 2*c4] = make_uint2(l0, l1);                \
        }                                                                         \
    }

    float acc[NB][4];
    #pragma unroll
    for (int n = 0; n < NB; n++)
        #pragma unroll
        for (int q = 0; q < 4; q++) acc[n][q] = 0.f;

    // ldmatrix per-lane row offset: rows wm*16 + (lane&15), chunk lane>>4
    unsigned lmoff = (unsigned)((wm*16 + (lane & 15))*SV + (lane >> 4)*4);

    STAGE(0, 0);
    __syncthreads();

    for (int tap = 0; tap < 9; tap++) {
        int cur = tap & 1, nxt = cur ^ 1;
        if (tap < 8) STAGE(tap + 1, nxt);
        const unsigned* vh = Vh[cur];
        const unsigned* vl = Vl[cur];
        #pragma unroll
        for (int ks = 0; ks < 4; ks++) {
            unsigned ahi[4], alo[4];
            ldsm4(ahi, vh + lmoff + ks*8);
            ldsm4(alo, vl + lmoff + ks*8);
            #pragma unroll
            for (int nb = 0; nb < NB; nb++) {
                uint4 wv = Wf[cur*WFRAG + ((ks*2 + wn)*NB + nb)*32 + lane];
                unsigned bhi[2] = { wv.x, wv.y };
                unsigned blo[2] = { wv.z, wv.w };
                mma_bf16(acc[nb], ahi, bhi);
                mma_bf16(acc[nb], alo, bhi);
                mma_bf16(acc[nb], ahi, blo);
            }
        }
        __syncthreads();
    }
    #undef STAGE

    // epilogue
    int px0 = pbase + wm*16 + l4;
    #pragma unroll
    for (int nb = 0; nb < NB; nb++) {
        int o = (MODE ? wn*32 : wn*16) + nb*8 + 2*t4;
        if (MODE) {
            float b0 = bias[lvl*CC + o], b1 = bias[lvl*CC + o + 1];
            *(float2*)(g_dc + (size_t)px0*CC + o)     = make_float2(acc[nb][0] + b0, acc[nb][1] + b1);
            *(float2*)(g_dc + (size_t)(px0+8)*CC + o) = make_float2(acc[nb][2] + b0, acc[nb][3] + b1);
        } else {
            if (o < NOFF) {
                float b0 = bias[lvl*NOFF + o];
                g_off[(size_t)px0*NOFF + o]     = acc[nb][0] + b0;
                g_off[(size_t)(px0+8)*NOFF + o] = acc[nb][2] + b0;
            }
            if (o + 1 < NOFF) {
                float b1 = bias[lvl*NOFF + o + 1];
                g_off[(size_t)px0*NOFF + o + 1]     = acc[nb][1] + b1;
                g_off[(size_t)(px0+8)*NOFF + o + 1] = acc[nb][3] + b1;
            }
        }
    }
}

// ---------------- SE reduce (partials, no atomics) + gate ----------------
__global__ void reduce_k(int h, int w)
{
    __shared__ float red[256];
    int blk = blockIdx.x; int b = blk >> 5; int slice = blk & 31;
    int tid = threadIdx.x;
    int c = tid & 63; int g = tid >> 6;
    int npix = h * w; int per = npix >> 5;
    float s = 0.f;
    int end = (slice + 1) * per;
    for (int p = slice*per + g; p < end; p += 4)
        s += g_dc[((size_t)b*npix + p)*CC + c];
    red[tid] = s;
    __syncthreads();
    if (g == 0)
        g_part[slice][b*CC + c] = red[c] + red[64 + c] + red[128 + c] + red[192 + c];
}

__global__ void gate_k(const float* __restrict__ se_w1, const float* __restrict__ se_b1,
                       const float* __restrict__ se_w2, const float* __restrict__ se_b2,
                       int lvl, int npix)
{
    __shared__ float mean[64];
    __shared__ float hid[4];
    int b = blockIdx.x; int tid = threadIdx.x;
    float m = 0.f;
    #pragma unroll
    for (int s = 0; s < 32; s++) m += g_part[s][b*CC + tid];
    mean[tid] = m / (float)npix;
    __syncthreads();
    if (tid < 4) {
        float a = se_b1[lvl*4 + tid];
        for (int cc = 0; cc < CC; cc++) a += se_w1[(lvl*4 + tid)*CC + cc] * mean[cc];
        hid[tid] = fmaxf(a, 0.f);
    }
    __syncthreads();
    float a = se_b2[lvl*CC + tid];
    #pragma unroll
    for (int r = 0; r < 4; r++) a += se_w2[(lvl*CC + tid)*4 + r] * hid[r];
    g_gates[b*CC + tid] = 1.f / (1.f + expf(-a));
}

// ---------------- gate + bilinear upsample ----------------
__global__ void upsample_k(int lvl, int h, int w)
{
    int i = blockIdx.x * blockDim.x + threadIdx.x;
    if (i >= BB*HH*WW*CC) return;
    int c = i & 63; int p = i >> 6;
    int X = p & 127; p >>= 7; int Y = p & 127; int b = p >> 7;
    float g = g_gates[b*CC + c];
    float v;
    if (h == HH) {
        v = g_dc[i];
    } else {
        float sc = (float)h * (1.f/128.f);
        float sy = fminf(fmaxf((Y + 0.5f)*sc - 0.5f, 0.f), (float)(h-1));
        float sx = fminf(fmaxf((X + 0.5f)*sc - 0.5f, 0.f), (float)(w-1));
        int y0 = (int)sy; int y1 = min(y0+1, h-1); float wy = sy - (float)y0;
        int x0 = (int)sx; int x1 = min(x0+1, w-1); float wx = sx - (float)x0;
        const float* base = g_dc + (size_t)b*h*w*CC + c;
        float v00 = base[((size_t)y0*w + x0)*CC];
        float v01 = base[((size_t)y0*w + x1)*CC];
        float v10 = base[((size_t)y1*w + x0)*CC];
        float v11 = base[((size_t)y1*w + x1)*CC];
        v = (1.f-wy)*((1.f-wx)*v00 + wx*v01) + wy*((1.f-wx)*v10 + wx*v11);
    }
    g_feats[lvl][i] = g * v;
}

// ---------------- fuse: cumulative 1x1 over 4 levels ----------------
__global__ void fuse_k(const float* __restrict__ fuse_b, float* __restrict__ out)
{
    __shared__ float sf[32*256];
    int pbase = blockIdx.x * 32;
    int tid = threadIdx.x;              // 256
    for (int t = tid; t < 32*256; t += 256) {
        int px = t >> 8; int jc = t & 255; int j = jc >> 6; int c = jc & 63;
        sf[t] = g_feats[j][(size_t)(pbase + px)*CC + c];
    }
    __syncthreads();
    int o = tid & 63; int pq = tid >> 6;
    float acc[8];
    #pragma unroll
    for (int q = 0; q < 8; q++) acc[q] = 0.f;
    const float4* wr = (const float4*)g_wcumT;
    #pragma unroll 4
    for (int j = 0; j < 64; j++) {
        float4 ww = wr[j*64 + o];
        #pragma unroll
        for (int q = 0; q < 8; q++) {
            float4 sv = ((const float4*)sf)[(pq*8 + q)*64 + j];
            acc[q] += ww.x*sv.x + ww.y*sv.y + ww.z*sv.z + ww.w*sv.w;
        }
    }
    float bias = fuse_b[o];
    __syncthreads();
    float* sout = sf;
    #pragma unroll
    for (int q = 0; q < 8; q++) sout[o*32 + pq*8 + q] = acc[q] + bias;
    __syncthreads();
    int X0 = pbase & 127; int r = pbase >> 7; int Y = r & 127; int b = r >> 7;
    for (int t = tid; t < 64*8; t += 256) {
        int oo = t >> 3; int q = t & 7;
        float4 v = ((const float4*)sout)[oo*8 + q];
        *(float4*)(out + (((size_t)(b*CC + oo)*HH + Y)*WW + X0 + q*4)) = v;
    }
}

// ---------------- launch ----------------
extern "C" void kernel_launch(void* const* d_in, const int* in_sizes, int n_in,
                              void* d_out, int out_size)
{
    const float* x      = (const float*)d_in[0];
    const float* off_w  = (const float*)d_in[1];
    const float* off_b  = (const float*)d_in[2];
    const float* dc_w   = (const float*)d_in[3];
    const float* dc_b   = (const float*)d_in[4];
    const float* se_w1  = (const float*)d_in[5];
    const float* se_b1  = (const float*)d_in[6];
    const float* se_w2  = (const float*)d_in[7];
    const float* se_b2  = (const float*)d_in[8];
    const float* fuse_w = (const float*)d_in[9];
    const float* fuse_b = (const float*)d_in[10];
    float* out = (float*)d_out;

    // smem: V (9216 u32) + W frags (8*WFRAG u32) + meta (2304 u32, deform only)
    const int SMEM_DEF = (9216 + 8*1024 + 2304) * 4;   // 78848
    const int SMEM_OFF = (9216 + 8*512) * 4;           // 53248
    cudaFuncSetAttribute(conv_mma_k<1>, cudaFuncAttributeMaxDynamicSharedMemorySize, SMEM_DEF);
    cudaFuncSetAttribute(conv_mma_k<0>, cudaFuncAttributeMaxDynamicSharedMemorySize, SMEM_OFF);

    prep_k<<<(LL*9*4*2*4*32 + 255)/256, 256>>>(off_w, dc_w, fuse_w);
    to_nhwc_k<<<BB*HH*4, 256>>>(x);

    for (int l = 0; l < LL; l++) {
        int h = HH >> l, w = WW >> l;
        int usex = (l == 0);
        int grid = (BB*h*w)/64;
        if (l > 0)
            down_k<<<(BB*h*w*CC + 255)/256, 256>>>(h, w);
        conv_mma_k<0><<<grid, 256, SMEM_OFF>>>(off_b, l, h, w, usex);
        conv_mma_k<1><<<grid, 256, SMEM_DEF>>>(dc_b, l, h, w, usex);
        reduce_k<<<BB*32, 256>>>(h, w);
        gate_k<<<BB, 64>>>(se_w1, se_b1, se_w2, se_b2, l, h*w);
        upsample_k<<<(BB*HH*WW*CC + 255)/256, 256>>>(l, h, w);
    }
    fuse_k<<<(BB*HH*WW)/32, 256>>>(fuse_b, out);
}

// round 5
// speedup vs baseline: 9.7537x; 1.2612x over previous
#include <cuda_runtime.h>
#include <cuda_bf16.h>

#define BB 4
#define CC 64
#define HH 128
#define WW 128
#define LL 4
#define NOFF 18
#define SV 36   // V row stride in u32 (144B, 16B-aligned rows for ldmatrix)

// ---------------- scratch ----------------
__device__ float g_xnhwc[BB*HH*WW*CC];
__device__ float g_curN [BB*HH*WW*CC];
__device__ float g_off  [BB*HH*WW*NOFF];
__device__ float g_dc   [BB*HH*WW*CC];
__device__ float g_feats[LL][BB*HH*WW*CC];
__device__ float g_gates[BB*CC];
__device__ float g_sum  [BB*CC];
__device__ float g_wcumT[64*64*4];           // [j][o] float4 cumulative fuse weights
__device__ uint4 g_WdF[LL*9*1024];           // deform W fragments: [(ks*2+wn)*4+nb]*32+lane
__device__ uint4 g_WoF[LL*9*512];            // offset W fragments: [(ks*2+wn)*2+nb]*32+lane

// Dekker split of 2 floats into bf16x2 hi + bf16x2 lo (exact residual)
__device__ __forceinline__ void split2(float v0, float v1, unsigned& hi, unsigned& lo) {
    unsigned h;
    asm("cvt.rn.bf16x2.f32 %0, %1, %2;" : "=r"(h) : "f"(v1), "f"(v0));
    float h0 = __uint_as_float(h << 16);
    float h1 = __uint_as_float(h & 0xffff0000u);
    float r0 = v0 - h0, r1 = v1 - h1;
    unsigned l;
    asm("cvt.rn.bf16x2.f32 %0, %1, %2;" : "=r"(l) : "f"(r1), "f"(r0));
    hi = h; lo = l;
}

__device__ __forceinline__ void mma_bf16(float c[4], const unsigned a[4], const unsigned b[2]) {
    asm volatile("mma.sync.aligned.m16n8k16.row.col.f32.bf16.bf16.f32 "
        "{%0,%1,%2,%3}, {%4,%5,%6,%7}, {%8,%9}, {%0,%1,%2,%3};"
        : "+f"(c[0]), "+f"(c[1]), "+f"(c[2]), "+f"(c[3])
        : "r"(a[0]), "r"(a[1]), "r"(a[2]), "r"(a[3]), "r"(b[0]), "r"(b[1]));
}
__device__ __forceinline__ void ldsm4(unsigned r[4], const unsigned* ptr) {
    unsigned addr = (unsigned)__cvta_generic_to_shared(ptr);
    asm volatile("ldmatrix.sync.aligned.m8n8.x4.shared.b16 {%0,%1,%2,%3}, [%4];"
        : "=r"(r[0]), "=r"(r[1]), "=r"(r[2]), "=r"(r[3]) : "r"(addr));
}

// ---------------- prep: fragment-ordered weights + cumulative fuse ----------
__global__ void prep_k(const float* __restrict__ off_w,
                       const float* __restrict__ dc_w,
                       const float* __restrict__ fuse_w)
{
    int i = blockIdx.x * blockDim.x + threadIdx.x;
    if (i < LL*9*4*2*4*32) {            // deform fragments
        int lane = i & 31; int r = i >> 5;
        int nb = r & 3; r >>= 2; int wn = r & 1; r >>= 1;
        int ks = r & 3; r >>= 2; int tap = r % 9; int l = r / 9;
        int t4 = lane & 3, l4 = lane >> 2;
        int o = wn*32 + nb*8 + l4;
        int c2a = ks*8 + t4, c2b = c2a + 4;
        float va0 = dc_w[((l*CC + o)*CC + 2*c2a)*9 + tap];
        float va1 = dc_w[((l*CC + o)*CC + 2*c2a + 1)*9 + tap];
        float vb0 = dc_w[((l*CC + o)*CC + 2*c2b)*9 + tap];
        float vb1 = dc_w[((l*CC + o)*CC + 2*c2b + 1)*9 + tap];
        unsigned ha, la, hb, lb;
        split2(va0, va1, ha, la); split2(vb0, vb1, hb, lb);
        g_WdF[(size_t)(l*9 + tap)*1024 + ((ks*2 + wn)*4 + nb)*32 + lane] = make_uint4(ha, hb, la, lb);
    }
    if (i < LL*9*4*2*2*32) {            // offset fragments (padded outputs)
        int lane = i & 31; int r = i >> 5;
        int nb = r & 1; r >>= 1; int wn = r & 1; r >>= 1;
        int ks = r & 3; r >>= 2; int tap = r % 9; int l = r / 9;
        int t4 = lane & 3, l4 = lane >> 2;
        int o = wn*16 + nb*8 + l4;
        int c2a = ks*8 + t4, c2b = c2a + 4;
        float va0 = 0.f, va1 = 0.f, vb0 = 0.f, vb1 = 0.f;
        if (o < NOFF) {
            va0 = off_w[((l*NOFF + o)*CC + 2*c2a)*9 + tap];
            va1 = off_w[((l*NOFF + o)*CC + 2*c2a + 1)*9 + tap];
            vb0 = off_w[((l*NOFF + o)*CC + 2*c2b)*9 + tap];
            vb1 = off_w[((l*NOFF + o)*CC + 2*c2b + 1)*9 + tap];
        }
        unsigned ha, la, hb, lb;
        split2(va0, va1, ha, la); split2(vb0, vb1, hb, lb);
        g_WoF[(size_t)(l*9 + tap)*512 + ((ks*2 + wn)*2 + nb)*32 + lane] = make_uint4(ha, hb, la, lb);
    }
    if (i < 64*64*4) {                  // wcumT[(j*64+o)*4+t]
        int t = i & 3; int o = (i >> 2) & 63; int j = i >> 8;
        int e = j*4 + t; int lev = e >> 6; int c = e & 63;
        float s = 0.f;
        for (int u = 0; u <= lev; u++) s += fuse_w[o*(LL*CC) + u*CC + c];
        g_wcumT[i] = s;
    }
}

// ---------------- NCHW -> NHWC (smem-tiled transpose) ----------------
__global__ void to_nhwc_k(const float* __restrict__ x)
{
    __shared__ float t[64][33];
    int blk = blockIdx.x;
    int xt = blk & 3; int r = blk >> 2; int y = r & 127; int b = r >> 7;
    int x0 = xt * 32;
    int tid = threadIdx.x;              // 256
    int xx = tid & 31, cg = tid >> 5;
    #pragma unroll
    for (int pass = 0; pass < 8; pass++) {
        int c = pass*8 + cg;
        t[c][xx] = x[((size_t)(b*CC + c)*HH + y)*WW + x0 + xx];
    }
    __syncthreads();
    int c = tid & 63, xg = tid >> 6;
    #pragma unroll
    for (int pass = 0; pass < 8; pass++) {
        int xo = pass*4 + xg;
        g_xnhwc[((size_t)((b*HH + y)*WW) + x0 + xo)*CC + c] = t[c][xo];
    }
}

// ---------------- unified conv via mma + ldmatrix, 64 px/block ---------------
// MODE 0 = offset conv (32 padded outputs), MODE 1 = deform conv (64 outputs)
template<int MODE>
__global__ void __launch_bounds__(256, 3) conv_mma_k(
    const float* __restrict__ bias, int lvl, int h, int w, int use_x)
{
    constexpr int NB    = MODE ? 4 : 2;
    constexpr int WFRAG = MODE ? 1024 : 512;   // uint4 per tap
    extern __shared__ unsigned smem[];
    unsigned* Vh[2] = { smem, smem + 2304 };
    unsigned* Vl[2] = { smem + 4608, smem + 6912 };
    int*   s_y0 = (int*)(smem + 9216);         // meta (MODE 1 only)
    int*   s_x0 = s_y0 + 576;
    float* s_wy = (float*)(s_x0 + 576);
    float* s_wx = s_wy + 576;
    __shared__ float sred[64];

    int tid = threadIdx.x;
    int lane = tid & 31, warp = tid >> 5;
    int wm = warp & 3, wn = warp >> 2;
    int t4 = lane & 3, l4 = lane >> 2;
    int pbase = blockIdx.x * 64;
    const float* src = use_x ? g_xnhwc : g_curN;
    int hw = h * w;
    int b = pbase / hw;
    const float* sb0 = src + (size_t)b*hw*CC;

    if (MODE == 0) {
        // zero the SE accumulator for this level (consumed by the next deform+gate)
        if (blockIdx.x < BB && tid < 64) g_sum[blockIdx.x*64 + tid] = 0.f;
    }
    if (MODE) {
        if (tid < 64) sred[tid] = 0.f;
        for (int t = tid; t < 64*9; t += 256) {
            int px = t / 9, k = t % 9;
            int p = pbase + px;
            int x = p % w; int y = (p / w) % h;
            float dy = g_off[(size_t)p*NOFF + 2*k];
            float dx = g_off[(size_t)p*NOFF + 2*k + 1];
            float py  = (float)(y + k/3 - 1) + dy;
            float pxx = (float)(x + k%3 - 1) + dx;
            float y0f = floorf(py), x0f = floorf(pxx);
            s_y0[t] = (int)y0f; s_x0[t] = (int)x0f;
            s_wy[t] = py - y0f; s_wx[t] = pxx - x0f;
        }
        __syncthreads();
    }

    const uint4* __restrict__ Wlvl = (MODE ? g_WdF : g_WoF) + (size_t)lvl*9*WFRAG;
    int c4 = lane & 15, pxo = lane >> 4;

    #define STAGE(tap_, buf_) {                                                   \
        for (int step = 0; step < 4; step++) {                                    \
            int px = step*16 + warp*2 + pxo;                                      \
            int p = pbase + px;                                                   \
            float v0 = 0.f, v1 = 0.f, v2 = 0.f, v3 = 0.f;                         \
            if (MODE) {                                                           \
                int mt = px*9 + (tap_);                                           \
                const float* sb = sb0 + 4*c4;                                     \
                int y0 = s_y0[mt], x0 = s_x0[mt];                                 \
                float wy = s_wy[mt], wx = s_wx[mt];                               \
                bool yi0 = (unsigned)y0       < (unsigned)h;                      \
                bool yi1 = (unsigned)(y0 + 1) < (unsigned)h;                      \
                bool xi0 = (unsigned)x0       < (unsigned)w;                      \
                bool xi1 = (unsigned)(x0 + 1) < (unsigned)w;                      \
                if (yi0 && xi0) { float4 q = *(const float4*)(sb + ((size_t)y0    *w + x0    )*CC); float cw = (1.f-wy)*(1.f-wx); v0 += cw*q.x; v1 += cw*q.y; v2 += cw*q.z; v3 += cw*q.w; } \
                if (yi0 && xi1) { float4 q = *(const float4*)(sb + ((size_t)y0    *w + x0 + 1)*CC); float cw = (1.f-wy)*wx;       v0 += cw*q.x; v1 += cw*q.y; v2 += cw*q.z; v3 += cw*q.w; } \
                if (yi1 && xi0) { float4 q = *(const float4*)(sb + ((size_t)(y0+1)*w + x0    )*CC); float cw = wy*(1.f-wx);       v0 += cw*q.x; v1 += cw*q.y; v2 += cw*q.z; v3 += cw*q.w; } \
                if (yi1 && xi1) { float4 q = *(const float4*)(sb + ((size_t)(y0+1)*w + x0 + 1)*CC); float cw = wy*wx;             v0 += cw*q.x; v1 += cw*q.y; v2 += cw*q.z; v3 += cw*q.w; } \
            } else {                                                              \
                int x = p % w; int y = (p / w) % h;                               \
                int yy = y + (tap_)/3 - 1, xx = x + (tap_)%3 - 1;                 \
                if ((unsigned)yy < (unsigned)h && (unsigned)xx < (unsigned)w) {   \
                    float4 q = *(const float4*)(sb0 + ((size_t)yy*w + xx)*CC + 4*c4); \
                    v0 = q.x; v1 = q.y; v2 = q.z; v3 = q.w;                       \
                }                                                                 \
            }                                                                     \
            unsigned h0, l0, h1, l1;                                              \
            split2(v0, v1, h0, l0); split2(v2, v3, h1, l1);                       \
            *(uint2*)&Vh[buf_][px*SV + 2*c4] = make_uint2(h0, h1);                \
            *(uint2*)&Vl[buf_][px*SV + 2*c4] = make_uint2(l0, l1);                \
        }                                                                         \
    }

    float acc[NB][4];
    #pragma unroll
    for (int n = 0; n < NB; n++)
        #pragma unroll
        for (int q = 0; q < 4; q++) acc[n][q] = 0.f;

    unsigned lmoff = (unsigned)((wm*16 + (lane & 15))*SV + (lane >> 4)*4);

    STAGE(0, 0);
    __syncthreads();

    for (int tap = 0; tap < 9; tap++) {
        int cur = tap & 1, nxt = cur ^ 1;
        if (tap < 8) STAGE(tap + 1, nxt);
        const unsigned* vh = Vh[cur];
        const unsigned* vl = Vl[cur];
        const uint4* Wp = Wlvl + (size_t)tap*WFRAG + wn*NB*32 + lane;
        #pragma unroll
        for (int ks = 0; ks < 4; ks++) {
            unsigned ahi[4], alo[4];
            ldsm4(ahi, vh + lmoff + ks*8);
            ldsm4(alo, vl + lmoff + ks*8);
            #pragma unroll
            for (int nb = 0; nb < NB; nb++) {
                uint4 wv = __ldg(Wp + (ks*2*NB + nb)*32);
                unsigned bhi[2] = { wv.x, wv.y };
                unsigned blo[2] = { wv.z, wv.w };
                mma_bf16(acc[nb], ahi, bhi);
                mma_bf16(acc[nb], alo, bhi);
                mma_bf16(acc[nb], ahi, blo);
            }
        }
        __syncthreads();
    }
    #undef STAGE

    // epilogue + (MODE 1) fused SE partial reduction
    int px0 = pbase + wm*16 + l4;
    #pragma unroll
    for (int nb = 0; nb < NB; nb++) {
        int o = (MODE ? wn*32 : wn*16) + nb*8 + 2*t4;
        if (MODE) {
            float b0 = bias[lvl*CC + o], b1 = bias[lvl*CC + o + 1];
            float u0 = acc[nb][0] + b0, u1 = acc[nb][1] + b1;
            float u2 = acc[nb][2] + b0, u3 = acc[nb][3] + b1;
            *(float2*)(g_dc + (size_t)px0*CC + o)     = make_float2(u0, u1);
            *(float2*)(g_dc + (size_t)(px0+8)*CC + o) = make_float2(u2, u3);
            float s0 = u0 + u2, s1 = u1 + u3;
            #pragma unroll
            for (int sh = 4; sh < 32; sh <<= 1) {
                s0 += __shfl_xor_sync(0xffffffffu, s0, sh);
                s1 += __shfl_xor_sync(0xffffffffu, s1, sh);
            }
            if (l4 == 0) {
                atomicAdd(&sred[o], s0);
                atomicAdd(&sred[o + 1], s1);
            }
        } else {
            if (o < NOFF) {
                float b0 = bias[lvl*NOFF + o];
                g_off[(size_t)px0*NOFF + o]     = acc[nb][0] + b0;
                g_off[(size_t)(px0+8)*NOFF + o] = acc[nb][2] + b0;
            }
            if (o + 1 < NOFF) {
                float b1 = bias[lvl*NOFF + o + 1];
                g_off[(size_t)px0*NOFF + o + 1]     = acc[nb][1] + b1;
                g_off[(size_t)(px0+8)*NOFF + o + 1] = acc[nb][3] + b1;
            }
        }
    }
    if (MODE) {
        __syncthreads();
        if (tid < 64) atomicAdd(&g_sum[b*CC + tid], sred[tid]);
    }
}

// ---------------- SE gate (means already summed into g_sum) ----------------
__global__ void gate_k(const float* __restrict__ se_w1, const float* __restrict__ se_b1,
                       const float* __restrict__ se_w2, const float* __restrict__ se_b2,
                       int lvl, int npix)
{
    __shared__ float mean[64];
    __shared__ float hid[4];
    int b = blockIdx.x; int tid = threadIdx.x;
    mean[tid] = g_sum[b*CC + tid] / (float)npix;
    __syncthreads();
    if (tid < 4) {
        float a = se_b1[lvl*4 + tid];
        for (int cc = 0; cc < CC; cc++) a += se_w1[(lvl*4 + tid)*CC + cc] * mean[cc];
        hid[tid] = fmaxf(a, 0.f);
    }
    __syncthreads();
    float a = se_b2[lvl*CC + tid];
    #pragma unroll
    for (int r = 0; r < 4; r++) a += se_w2[(lvl*CC + tid)*4 + r] * hid[r];
    g_gates[b*CC + tid] = 1.f / (1.f + expf(-a));
}

// ---------------- gate + bilinear upsample, fused with next-level downsample --
__global__ void upsample_k(int lvl, int h, int w, int do_down)
{
    const int upsN = BB*HH*WW*CC;
    int i = blockIdx.x * blockDim.x + threadIdx.x;
    if (i < upsN) {
        int c = i & 63; int p = i >> 6;
        int X = p & 127; p >>= 7; int Y = p & 127; int b = p >> 7;
        float g = g_gates[b*CC + c];
        float v;
        if (h == HH) {
            v = g_dc[i];
        } else {
            float sc = (float)h * (1.f/128.f);
            float sy = fminf(fmaxf((Y + 0.5f)*sc - 0.5f, 0.f), (float)(h-1));
            float sx = fminf(fmaxf((X + 0.5f)*sc - 0.5f, 0.f), (float)(w-1));
            int y0 = (int)sy; int y1 = min(y0+1, h-1); float wy = sy - (float)y0;
            int x0 = (int)sx; int x1 = min(x0+1, w-1); float wx = sx - (float)x0;
            const float* base = g_dc + (size_t)b*h*w*CC + c;
            float v00 = base[((size_t)y0*w + x0)*CC];
            float v01 = base[((size_t)y0*w + x1)*CC];
            float v10 = base[((size_t)y1*w + x0)*CC];
            float v11 = base[((size_t)y1*w + x1)*CC];
            v = (1.f-wy)*((1.f-wx)*v00 + wx*v01) + wy*((1.f-wx)*v10 + wx*v11);
        }
        g_feats[lvl][i] = g * v;
    } else if (do_down) {
        int j = i - upsN;
        int h2 = h >> 1, w2 = w >> 1;
        int total = BB*h2*w2*CC;
        if (j >= total) return;
        int c = j & 63; int p = j >> 6;
        int x = p % w2; int t = p / w2; int y = t % h2; int b = t / h2;
        float g = g_gates[b*CC + c];
        size_t base = ((size_t)(b*h + 2*y)*w + 2*x)*CC + c;
        float v = g_dc[base] + g_dc[base + CC] + g_dc[base + (size_t)w*CC] + g_dc[base + (size_t)w*CC + CC];
        g_curN[j] = 0.25f * g * v;
    }
}

// ---------------- fuse: cumulative 1x1 over 4 levels ----------------
__global__ void fuse_k(const float* __restrict__ fuse_b, float* __restrict__ out)
{
    __shared__ float sf[32*256];
    int pbase = blockIdx.x * 32;
    int tid = threadIdx.x;              // 256
    for (int t = tid; t < 32*256; t += 256) {
        int px = t >> 8; int jc = t & 255; int j = jc >> 6; int c = jc & 63;
        sf[t] = g_feats[j][(size_t)(pbase + px)*CC + c];
    }
    __syncthreads();
    int o = tid & 63; int pq = tid >> 6;
    float acc[8];
    #pragma unroll
    for (int q = 0; q < 8; q++) acc[q] = 0.f;
    const float4* wr = (const float4*)g_wcumT;
    #pragma unroll 4
    for (int j = 0; j < 64; j++) {
        float4 ww = wr[j*64 + o];
        #pragma unroll
        for (int q = 0; q < 8; q++) {
            float4 sv = ((const float4*)sf)[(pq*8 + q)*64 + j];
            acc[q] += ww.x*sv.x + ww.y*sv.y + ww.z*sv.z + ww.w*sv.w;
        }
    }
    float bias = fuse_b[o];
    __syncthreads();
    float* sout = sf;
    #pragma unroll
    for (int q = 0; q < 8; q++) sout[o*32 + pq*8 + q] = acc[q] + bias;
    __syncthreads();
    int X0 = pbase & 127; int r = pbase >> 7; int Y = r & 127; int b = r >> 7;
    for (int t = tid; t < 64*8; t += 256) {
        int oo = t >> 3; int q = t & 7;
        float4 v = ((const float4*)sout)[oo*8 + q];
        *(float4*)(out + (((size_t)(b*CC + oo)*HH + Y)*WW + X0 + q*4)) = v;
    }
}

// ---------------- launch ----------------
extern "C" void kernel_launch(void* const* d_in, const int* in_sizes, int n_in,
                              void* d_out, int out_size)
{
    const float* x      = (const float*)d_in[0];
    const float* off_w  = (const float*)d_in[1];
    const float* off_b  = (const float*)d_in[2];
    const float* dc_w   = (const float*)d_in[3];
    const float* dc_b   = (const float*)d_in[4];
    const float* se_w1  = (const float*)d_in[5];
    const float* se_b1  = (const float*)d_in[6];
    const float* se_w2  = (const float*)d_in[7];
    const float* se_b2  = (const float*)d_in[8];
    const float* fuse_w = (const float*)d_in[9];
    const float* fuse_b = (const float*)d_in[10];
    float* out = (float*)d_out;

    const int SMEM_DEF = (9216 + 2304) * 4;   // 46080
    const int SMEM_OFF = 9216 * 4;            // 36864
    cudaFuncSetAttribute(conv_mma_k<1>, cudaFuncAttributeMaxDynamicSharedMemorySize, SMEM_DEF);
    cudaFuncSetAttribute(conv_mma_k<0>, cudaFuncAttributeMaxDynamicSharedMemorySize, SMEM_OFF);

    prep_k<<<(LL*9*4*2*4*32 + 255)/256, 256>>>(off_w, dc_w, fuse_w);
    to_nhwc_k<<<BB*HH*4, 256>>>(x);

    for (int l = 0; l < LL; l++) {
        int h = HH >> l, w = WW >> l;
        int usex = (l == 0);
        int grid = (BB*h*w)/64;
        conv_mma_k<0><<<grid, 256, SMEM_OFF>>>(off_b, l, h, w, usex);
        conv_mma_k<1><<<grid, 256, SMEM_DEF>>>(dc_b, l, h, w, usex);
        gate_k<<<BB, 64>>>(se_w1, se_b1, se_w2, se_b2, l, h*w);
        int do_down = (l < LL-1);
        int downN = do_down ? (BB*(h>>1)*(w>>1)*CC) : 0;
        upsample_k<<<(BB*HH*WW*CC + downN + 255)/256, 256>>>(l, h, w, do_down);
    }
    fuse_k<<<(BB*HH*WW)/32, 256>>>(fuse_b, out);
}